// round 1
// baseline (speedup 1.0000x reference)
#include <cuda_runtime.h>

#define N_NODES 40000
#define N_EDGES 640000
#define HID 128
#define N_LAYERS 4
#define NUM_GRAPHS 256

// GEMM tile config (classic 128x128x8 SIMT fp32, 256 threads, 8x8 per thread)
#define BM 128
#define BN 128
#define BK 8
#define TM 8
#define TN 8
#define GT 256

// ---------------------------------------------------------------------------
// Scratch (static device allocations; ~800 MB total)
// ---------------------------------------------------------------------------
__device__ float g_h[2][(size_t)N_NODES * HID];     // ping-pong node features
__device__ float g_e[2][(size_t)N_EDGES * HID];     // ping-pong edge features
__device__ float g_P[(size_t)N_NODES * 4 * HID];    // [N,512]: h@Wm_s | h@Wm_r | h@We_s | h@We_r
__device__ float g_agg[(size_t)N_NODES * HID];      // scatter-add target

// ---------------------------------------------------------------------------
// Vector reduction to global memory (sm_90+: red.global.add.v4.f32)
// ---------------------------------------------------------------------------
__device__ __forceinline__ void red_add_v4(float* addr, float a, float b, float c, float d) {
    asm volatile("red.global.add.v4.f32 [%0], {%1, %2, %3, %4};"
                 :: "l"(addr), "f"(a), "f"(b), "f"(c), "f"(d)
                 : "memory");
}

// ---------------------------------------------------------------------------
// Shared GEMM core: C_tile(128x128) = A[m0:m0+128, 0:128] @ B[0:128, 0:128]
// lda = ldb = 128 always in this problem (all feature widths are 128).
// ---------------------------------------------------------------------------
__device__ __forceinline__ void gemm_core(
    const float* __restrict__ A, const float* __restrict__ B,
    int m0, int M, bool guard,
    float (&As)[BK][BM], float (&Bs)[BK][BN], float (&acc)[TM][TN])
{
    const int tid  = threadIdx.x;
    const int aRow = tid >> 1;          // 0..127
    const int aCol = (tid & 1) << 2;    // 0 or 4
    const int bRow = tid >> 5;          // 0..7
    const int bCol = (tid & 31) << 2;   // 0..124
    const int tRow = tid >> 4;          // 0..15
    const int tCol = tid & 15;          // 0..15

#pragma unroll
    for (int i = 0; i < TM; i++)
#pragma unroll
        for (int j = 0; j < TN; j++) acc[i][j] = 0.f;

    const bool aValid = (!guard) || ((m0 + aRow) < M);
    const float* Ap = A + (size_t)(m0 + aRow) * HID + aCol;
    const float* Bp = B + (size_t)bRow * HID + bCol;

    for (int kt = 0; kt < HID; kt += BK) {
        float4 av = aValid ? *(const float4*)(Ap + kt) : make_float4(0.f, 0.f, 0.f, 0.f);
        As[aCol + 0][aRow] = av.x;
        As[aCol + 1][aRow] = av.y;
        As[aCol + 2][aRow] = av.z;
        As[aCol + 3][aRow] = av.w;
        *(float4*)&Bs[bRow][bCol] = *(const float4*)(Bp + (size_t)kt * HID);
        __syncthreads();
#pragma unroll
        for (int bk = 0; bk < BK; bk++) {
            float4 a0 = *(const float4*)&As[bk][tRow * TM];
            float4 a1 = *(const float4*)&As[bk][tRow * TM + 4];
            float4 b0 = *(const float4*)&Bs[bk][tCol * TN];
            float4 b1 = *(const float4*)&Bs[bk][tCol * TN + 4];
            float ra[TM] = {a0.x, a0.y, a0.z, a0.w, a1.x, a1.y, a1.z, a1.w};
            float rb[TN] = {b0.x, b0.y, b0.z, b0.w, b1.x, b1.y, b1.z, b1.w};
#pragma unroll
            for (int i = 0; i < TM; i++)
#pragma unroll
                for (int j = 0; j < TN; j++)
                    acc[i][j] += ra[i] * rb[j];
        }
        __syncthreads();
    }
}

// ---------------------------------------------------------------------------
// Generic N=128 GEMM with optional bias / accumulate-into-C epilogue.
// ---------------------------------------------------------------------------
template<bool BIAS, bool ACCUM>
__global__ __launch_bounds__(GT)
void sgemm128(int M, const float* __restrict__ A, const float* __restrict__ B,
              const float* __restrict__ bias, float* __restrict__ C, int ldc)
{
    __shared__ float As[BK][BM];
    __shared__ float Bs[BK][BN];
    float acc[TM][TN];
    const int m0 = blockIdx.x * BM;
    gemm_core(A, B, m0, M, true, As, Bs, acc);

    const int tRow = threadIdx.x >> 4;
    const int tCol = threadIdx.x & 15;
    const int col  = tCol * TN;

    float4 bias0 = make_float4(0.f, 0.f, 0.f, 0.f), bias1 = bias0;
    if (BIAS) {
        bias0 = *(const float4*)(bias + col);
        bias1 = *(const float4*)(bias + col + 4);
    }
#pragma unroll
    for (int i = 0; i < TM; i++) {
        int m = m0 + tRow * TM + i;
        if (m >= M) continue;
        float* Cp = C + (size_t)m * ldc + col;
        float4 v0 = make_float4(acc[i][0], acc[i][1], acc[i][2], acc[i][3]);
        float4 v1 = make_float4(acc[i][4], acc[i][5], acc[i][6], acc[i][7]);
        if (BIAS) {
            v0.x += bias0.x; v0.y += bias0.y; v0.z += bias0.z; v0.w += bias0.w;
            v1.x += bias1.x; v1.y += bias1.y; v1.z += bias1.z; v1.w += bias1.w;
        }
        if (ACCUM) {
            float4 c0 = *(const float4*)Cp;
            float4 c1 = *(const float4*)(Cp + 4);
            v0.x += c0.x; v0.y += c0.y; v0.z += c0.z; v0.w += c0.w;
            v1.x += c1.x; v1.y += c1.y; v1.z += c1.z; v1.w += c1.w;
        }
        *(float4*)Cp       = v0;
        *(float4*)(Cp + 4) = v1;
    }
}

// ---------------------------------------------------------------------------
// Fused edge GEMM:
//   blockIdx.x == 0:  msg = e@Wm_e + bm + P[s,0:128] + P[r,128:256]  -> red-add agg[r]
//   blockIdx.x == 1:  e'  = e@We_e + be + P[s,256:384] + P[r,384:512] -> store e_out
// E = 640000 is divisible by BM, so no row guards.
// ---------------------------------------------------------------------------
__global__ __launch_bounds__(GT)
void edge_gemm(const float* __restrict__ E_in,
               const float* __restrict__ Wm_e, const float* __restrict__ We_e,
               const float* __restrict__ bm,   const float* __restrict__ be,
               const float* __restrict__ P,
               const int* __restrict__ send,   const int* __restrict__ rec,
               float* __restrict__ agg,        float* __restrict__ e_out)
{
    __shared__ float As[BK][BM];
    __shared__ float Bs[BK][BN];
    float acc[TM][TN];
    const int which = blockIdx.x;        // 0 = message path, 1 = edge-update path
    const int m0    = blockIdx.y * BM;
    gemm_core(E_in, which ? We_e : Wm_e, m0, N_EDGES, false, As, Bs, acc);

    const int tRow = threadIdx.x >> 4;
    const int tCol = threadIdx.x & 15;
    const int col  = tCol * TN;
    const float* bv = which ? be : bm;
    const float4 bias0 = *(const float4*)(bv + col);
    const float4 bias1 = *(const float4*)(bv + col + 4);

    if (which == 0) {
#pragma unroll
        for (int i = 0; i < TM; i++) {
            const int m = m0 + tRow * TM + i;
            const int s = send[m];
            const int r = rec[m];
            const float* Ps = P + (size_t)s * 512 + col;          // h@Wm_s at send
            const float* Pr = P + (size_t)r * 512 + 128 + col;    // h@Wm_r at rec
            float4 p0 = *(const float4*)Ps, p1 = *(const float4*)(Ps + 4);
            float4 q0 = *(const float4*)Pr, q1 = *(const float4*)(Pr + 4);
            float* ap = agg + (size_t)r * HID + col;
            red_add_v4(ap,
                       acc[i][0] + bias0.x + p0.x + q0.x,
                       acc[i][1] + bias0.y + p0.y + q0.y,
                       acc[i][2] + bias0.z + p0.z + q0.z,
                       acc[i][3] + bias0.w + p0.w + q0.w);
            red_add_v4(ap + 4,
                       acc[i][4] + bias1.x + p1.x + q1.x,
                       acc[i][5] + bias1.y + p1.y + q1.y,
                       acc[i][6] + bias1.z + p1.z + q1.z,
                       acc[i][7] + bias1.w + p1.w + q1.w);
        }
    } else {
#pragma unroll
        for (int i = 0; i < TM; i++) {
            const int m = m0 + tRow * TM + i;
            const int s = send[m];
            const int r = rec[m];
            const float* Ps = P + (size_t)s * 512 + 256 + col;    // h@We_s at send
            const float* Pr = P + (size_t)r * 512 + 384 + col;    // h@We_r at rec
            float4 p0 = *(const float4*)Ps, p1 = *(const float4*)(Ps + 4);
            float4 q0 = *(const float4*)Pr, q1 = *(const float4*)(Pr + 4);
            float4 v0 = make_float4(acc[i][0] + bias0.x + p0.x + q0.x,
                                    acc[i][1] + bias0.y + p0.y + q0.y,
                                    acc[i][2] + bias0.z + p0.z + q0.z,
                                    acc[i][3] + bias0.w + p0.w + q0.w);
            float4 v1 = make_float4(acc[i][4] + bias1.x + p1.x + q1.x,
                                    acc[i][5] + bias1.y + p1.y + q1.y,
                                    acc[i][6] + bias1.z + p1.z + q1.z,
                                    acc[i][7] + bias1.w + p1.w + q1.w);
            float* op = e_out + (size_t)m * HID + col;
            *(float4*)op       = v0;
            *(float4*)(op + 4) = v1;
        }
    }
}

// ---------------------------------------------------------------------------
// Edge embedding: e0 = E[:,0:16] @ W[16,128] + b  (K=16, bandwidth bound)
// ---------------------------------------------------------------------------
__global__ __launch_bounds__(128)
void embed_e_kernel(const float* __restrict__ e_in, const float* __restrict__ W,
                    const float* __restrict__ b, float* __restrict__ out)
{
    __shared__ float Ws[16 * 128];
    __shared__ float bs[128];
    for (int i = threadIdx.x; i < 16 * 128; i += blockDim.x) Ws[i] = W[i];
    if (threadIdx.x < 128) bs[threadIdx.x] = b[threadIdx.x];
    __syncthreads();

    const int c = threadIdx.x;
    for (int k = blockIdx.x; k < N_EDGES; k += gridDim.x) {
        const float* er = e_in + (size_t)k * 16;
        float acc = bs[c];
#pragma unroll
        for (int j = 0; j < 16; j++) acc += er[j] * Ws[j * 128 + c];
        out[(size_t)k * HID + c] = acc;
    }
}

// ---------------------------------------------------------------------------
// Global add-pool: out[batch[n], :] += h[n, :]
// ---------------------------------------------------------------------------
__global__ __launch_bounds__(128)
void pool_kernel(const float* __restrict__ h, const int* __restrict__ batch,
                 float* __restrict__ out)
{
    const int n = blockIdx.x;
    const int c = threadIdx.x;
    const int g = batch[n];
    atomicAdd(&out[(size_t)g * HID + c], h[(size_t)n * HID + c]);
}

// ---------------------------------------------------------------------------
// Launch
// ---------------------------------------------------------------------------
extern "C" void kernel_launch(void* const* d_in, const int* in_sizes, int n_in,
                              void* d_out, int out_size)
{
    const float* h_in     = (const float*)d_in[0];
    const float* e_in     = (const float*)d_in[1];
    const int*   edge_idx = (const int*)  d_in[2];
    const int*   batch    = (const int*)  d_in[3];
    const float* W_embed  = (const float*)d_in[4];
    const float* b_embed  = (const float*)d_in[5];
    const float* W_eembed = (const float*)d_in[6];
    const float* b_eembed = (const float*)d_in[7];
    const float* Wm       = (const float*)d_in[8];
    const float* bm       = (const float*)d_in[9];
    const float* Wh       = (const float*)d_in[10];
    const float* bh       = (const float*)d_in[11];
    const float* We       = (const float*)d_in[12];
    const float* be       = (const float*)d_in[13];
    float*       out      = (float*)d_out;

    float *hbuf, *ebuf, *Pp, *aggp;
    cudaGetSymbolAddress((void**)&hbuf, g_h);
    cudaGetSymbolAddress((void**)&ebuf, g_e);
    cudaGetSymbolAddress((void**)&Pp,   g_P);
    cudaGetSymbolAddress((void**)&aggp, g_agg);

    float* hb[2] = { hbuf, hbuf + (size_t)N_NODES * HID };
    float* eb[2] = { ebuf, ebuf + (size_t)N_EDGES * HID };
    const int* send = edge_idx;
    const int* rec  = edge_idx + N_EDGES;

    const int MT = (N_NODES + BM - 1) / BM;   // 313 node row-tiles
    const int ET = N_EDGES / BM;              // 5000 edge row-tiles (exact)

    // Embeddings
    sgemm128<true, false><<<MT, GT>>>(N_NODES, h_in, W_embed, b_embed, hb[0], HID);
    embed_e_kernel<<<2048, 128>>>(e_in, W_eembed, b_eembed, eb[0]);

    int cur = 0;
    for (int l = 0; l < N_LAYERS; l++) {
        const float* Wm_l = Wm + (size_t)l * 384 * HID;
        const float* We_l = We + (size_t)l * 384 * HID;
        const float* Wh_l = Wh + (size_t)l * 256 * HID;
        const float* bm_l = bm + (size_t)l * HID;
        const float* bh_l = bh + (size_t)l * HID;
        const float* be_l = be + (size_t)l * HID;
        float* hcur = hb[cur];
        float* ecur = eb[cur];
        float* hnxt = hb[1 - cur];
        float* enxt = eb[1 - cur];

        // Node-side projections: P = h @ [Wm_s | Wm_r | We_s | We_r]  -> [N, 512]
        sgemm128<false, false><<<MT, GT>>>(N_NODES, hcur, Wm_l,             nullptr, Pp + 0,   512);
        sgemm128<false, false><<<MT, GT>>>(N_NODES, hcur, Wm_l + 128 * HID, nullptr, Pp + 128, 512);
        sgemm128<false, false><<<MT, GT>>>(N_NODES, hcur, We_l,             nullptr, Pp + 256, 512);
        sgemm128<false, false><<<MT, GT>>>(N_NODES, hcur, We_l + 128 * HID, nullptr, Pp + 384, 512);

        cudaMemsetAsync(aggp, 0, (size_t)N_NODES * HID * sizeof(float));

        // Fused edge GEMM + gather + scatter-add + edge update
        edge_gemm<<<dim3(2, ET), GT>>>(ecur, Wm_l + 256 * HID, We_l + 256 * HID,
                                       bm_l, be_l, Pp, send, rec, aggp, enxt);

        // h_new = [h | agg] @ Wh + bh
        sgemm128<true,  false><<<MT, GT>>>(N_NODES, hcur, Wh_l,             bh_l,    hnxt, HID);
        sgemm128<false, true ><<<MT, GT>>>(N_NODES, aggp, Wh_l + 128 * HID, nullptr, hnxt, HID);

        cur = 1 - cur;
    }

    // Global add pool
    cudaMemsetAsync(d_out, 0, (size_t)NUM_GRAPHS * HID * sizeof(float));
    pool_kernel<<<N_NODES, 128>>>(hb[cur], batch, out);
}

// round 4
// speedup vs baseline: 1.7277x; 1.7277x over previous
#include <cuda_runtime.h>
#include <cuda_bf16.h>
#include <cstdint>

#define N_NODES 40000
#define N_EDGES 640000
#define HID 128
#define N_LAYERS 4
#define NUM_GRAPHS 256

#define GT 256          // 8 warps per GEMM CTA
#define NODE_TILES 313  // ceil(40000/128)
#define EDGE_TILES 5000 // 640000/128

// SMEM tile geometry: 128 rows x 136 bf16 (stride 272B, 16B aligned, conflict-free ldmatrix)
#define LDB 272
#define TILE_BYTES 34816            // 128 * 272
#define SM_A_HI 0
#define SM_A_LO 34816
#define SM_B_HI 69632
#define SM_B_LO 104448
#define SMEM_SZ 139264

// ---------------------------------------------------------------------------
// Scratch
// ---------------------------------------------------------------------------
__device__ float g_h[2][(size_t)N_NODES * HID];
__device__ float g_e[2][(size_t)N_EDGES * HID];
__device__ float g_P[(size_t)N_NODES * 4 * HID];   // [N,512]: hWm_s | hWm_r | hWe_s | hWe_r
__device__ float g_agg[(size_t)N_NODES * HID];
// 33 weight slots: each = hi image (34816 B) + lo image (34816 B), padded row-major [n][k]
__device__ uint4 g_Bw[(size_t)33 * 4352];

// ---------------------------------------------------------------------------
// PTX helpers (baseline ISA only — no arch-suffix features)
// ---------------------------------------------------------------------------
__device__ __forceinline__ uint32_t smem_u32(const void* p) {
    uint32_t a;
    asm("{ .reg .u64 t; cvta.to.shared.u64 t, %1; cvt.u32.u64 %0, t; }" : "=r"(a) : "l"(p));
    return a;
}
__device__ __forceinline__ void red_add_v2(float* addr, float a, float b) {
    asm volatile("red.global.add.v2.f32 [%0], {%1, %2};"
                 :: "l"(addr), "f"(a), "f"(b) : "memory");
}
__device__ __forceinline__ void ldsm_x4(uint32_t addr, uint32_t r[4]) {
    asm volatile("ldmatrix.sync.aligned.m8n8.x4.shared.b16 {%0,%1,%2,%3}, [%4];"
                 : "=r"(r[0]), "=r"(r[1]), "=r"(r[2]), "=r"(r[3]) : "r"(addr));
}
__device__ __forceinline__ void mma_bf16(float c[4], const uint32_t a[4], uint32_t b0, uint32_t b1) {
    asm volatile("mma.sync.aligned.m16n8k16.row.col.f32.bf16.bf16.f32 "
                 "{%0,%1,%2,%3}, {%4,%5,%6,%7}, {%8,%9}, {%0,%1,%2,%3};"
                 : "+f"(c[0]), "+f"(c[1]), "+f"(c[2]), "+f"(c[3])
                 : "r"(a[0]), "r"(a[1]), "r"(a[2]), "r"(a[3]), "r"(b0), "r"(b1));
}

// ---------------------------------------------------------------------------
// fp32 -> bf16 hi/lo split
// ---------------------------------------------------------------------------
__device__ __forceinline__ uint32_t pack_hi_lo(float a, float b, uint32_t& lo_out) {
    __nv_bfloat16 ha = __float2bfloat16_rn(a), hb = __float2bfloat16_rn(b);
    float ra = a - __bfloat162float(ha), rb = b - __bfloat162float(hb);
    __nv_bfloat16 la = __float2bfloat16_rn(ra), lb = __float2bfloat16_rn(rb);
    lo_out = (uint32_t)__bfloat16_as_ushort(la) | ((uint32_t)__bfloat16_as_ushort(lb) << 16);
    return (uint32_t)__bfloat16_as_ushort(ha) | ((uint32_t)__bfloat16_as_ushort(hb) << 16);
}

// Stage A: fp32 [128][128] (row stride 128) -> hi/lo bf16 padded tiles in SMEM
template<bool GUARD>
__device__ __forceinline__ void stage_A(const float* __restrict__ A, int m0, int M,
                                        int tid, char* smem)
{
#pragma unroll
    for (int i = 0; i < 8; i++) {
        int c = tid + i * 256;
        int row = c >> 4;
        int k0 = (c & 15) << 3;
        float v[8];
        bool ok = (!GUARD) || (m0 + row < M);
        if (ok) {
            const float4* ap = (const float4*)(A + (size_t)(m0 + row) * HID + k0);
            float4 x0 = ap[0], x1 = ap[1];
            v[0] = x0.x; v[1] = x0.y; v[2] = x0.z; v[3] = x0.w;
            v[4] = x1.x; v[5] = x1.y; v[6] = x1.z; v[7] = x1.w;
        } else {
#pragma unroll
            for (int j = 0; j < 8; j++) v[j] = 0.f;
        }
        uint32_t hi[4], lo[4];
#pragma unroll
        for (int j = 0; j < 4; j++) hi[j] = pack_hi_lo(v[2 * j], v[2 * j + 1], lo[j]);
        uint32_t off = (uint32_t)(row * LDB + k0 * 2);
        *(uint4*)(smem + SM_A_HI + off) = make_uint4(hi[0], hi[1], hi[2], hi[3]);
        *(uint4*)(smem + SM_A_LO + off) = make_uint4(lo[0], lo[1], lo[2], lo[3]);
    }
}

// Stage B: copy pre-split hi+lo images (69632 B) from g_Bw slot
__device__ __forceinline__ void stage_B(int slot, int tid, char* smem)
{
    const uint4* src = g_Bw + (size_t)slot * 4352;
    uint4* dst = (uint4*)(smem + SM_B_HI);
#pragma unroll
    for (int i = 0; i < 17; i++) dst[tid + i * 256] = src[tid + i * 256];
}

// ---------------------------------------------------------------------------
// Core: 3-product bf16 MMA over full K=128. acc[mi][ni][4], warp = 32x64 region
// ---------------------------------------------------------------------------
__device__ __forceinline__ void mma_tile(uint32_t sb, int wid, int lane,
                                         float acc[2][8][4], bool zero)
{
    if (zero) {
#pragma unroll
        for (int mi = 0; mi < 2; mi++)
#pragma unroll
            for (int ni = 0; ni < 8; ni++)
#pragma unroll
                for (int j = 0; j < 4; j++) acc[mi][ni][j] = 0.f;
    }
    const int wm = wid & 3, wn = wid >> 2;
    const uint32_t lrow = (uint32_t)((lane & 15) * LDB + (lane >> 4) * 16);
    const uint32_t aBase = sb + SM_A_HI + wm * 32 * LDB + lrow;
    const uint32_t bBase = sb + SM_B_HI + wn * 64 * LDB + lrow;

#pragma unroll
    for (int ks = 0; ks < 8; ks++) {
        const uint32_t ko = ks * 32;
        uint32_t ah[2][4], al[2][4];
#pragma unroll
        for (int mi = 0; mi < 2; mi++) {
            ldsm_x4(aBase + mi * 16 * LDB + ko, ah[mi]);
            ldsm_x4(aBase + mi * 16 * LDB + ko + (SM_A_LO - SM_A_HI), al[mi]);
        }
#pragma unroll
        for (int nb = 0; nb < 4; nb++) {
            uint32_t bh[4], bl[4];
            ldsm_x4(bBase + nb * 16 * LDB + ko, bh);
            ldsm_x4(bBase + nb * 16 * LDB + ko + (SM_B_LO - SM_B_HI), bl);
#pragma unroll
            for (int half = 0; half < 2; half++) {
                const int ni = nb * 2 + half;
#pragma unroll
                for (int mi = 0; mi < 2; mi++) {
                    mma_bf16(acc[mi][ni], ah[mi], bh[half], bh[half + 2]);
                    mma_bf16(acc[mi][ni], ah[mi], bl[half], bl[half + 2]);
                    mma_bf16(acc[mi][ni], al[mi], bh[half], bh[half + 2]);
                }
            }
        }
    }
}

// ---------------------------------------------------------------------------
// Weight prep: 33 fp32 [K=128][N=128] blocks -> bf16 hi/lo padded [n][k] images
// slots: 0 = W_embed; per layer l: 1+8l+{0..2}=Wm{s,r,e}, {3..5}=We{s,r,e}, {6,7}=Wh{a,b}
// ---------------------------------------------------------------------------
__global__ __launch_bounds__(256)
void prep_weights(const float* __restrict__ W_embed, const float* __restrict__ Wm,
                  const float* __restrict__ Wh, const float* __restrict__ We)
{
    int t = blockIdx.x;
    const float* src;
    if (t == 0) src = W_embed;
    else {
        int tt = t - 1, l = tt >> 3, j = tt & 7;
        if (j < 3)      src = Wm + (size_t)l * 384 * HID + j * 16384;
        else if (j < 6) src = We + (size_t)l * 384 * HID + (j - 3) * 16384;
        else            src = Wh + (size_t)l * 256 * HID + (j - 6) * 16384;
    }
    char* dst = (char*)(g_Bw + (size_t)t * 4352);
    for (int i = threadIdx.x; i < 16384; i += 256) {
        int k = i >> 7, n = i & 127;
        float v = src[i];
        __nv_bfloat16 h = __float2bfloat16_rn(v);
        __nv_bfloat16 lo = __float2bfloat16_rn(v - __bfloat162float(h));
        uint32_t off = (uint32_t)(n * LDB + k * 2);
        *(__nv_bfloat16*)(dst + off) = h;
        *(__nv_bfloat16*)(dst + TILE_BYTES + off) = lo;
    }
}

// ---------------------------------------------------------------------------
// proj_gemm: P[:, y*128:(y+1)*128] = h @ Wblock[y] for y in 0..3  (grid: 313)
// slots used: sbase + {0,1,3,4}
// ---------------------------------------------------------------------------
__global__ __launch_bounds__(GT, 1)
void proj_gemm(const float* __restrict__ A, int sbase, float* __restrict__ C)
{
    extern __shared__ char smem[];
    uint32_t sb = smem_u32(smem);
    const int tid = threadIdx.x, wid = tid >> 5, lane = tid & 31;
    const int m0 = blockIdx.x * 128;
    const int wm = wid & 3, wn = wid >> 2;
    const int r4 = lane >> 2, c2 = (lane & 3) * 2;

    stage_A<true>(A, m0, N_NODES, tid, smem);
    float acc[2][8][4];

#pragma unroll
    for (int y = 0; y < 4; y++) {
        __syncthreads();                    // prior mma readers done / A staged
        stage_B(sbase + ((y < 2) ? y : y + 1), tid, smem);
        __syncthreads();
        mma_tile(sb, wid, lane, acc, true);

#pragma unroll
        for (int mi = 0; mi < 2; mi++) {
#pragma unroll
            for (int jh = 0; jh < 2; jh++) {
                int row = m0 + wm * 32 + mi * 16 + jh * 8 + r4;
                if (row >= N_NODES) continue;
                float* Cp = C + (size_t)row * 512 + y * 128;
#pragma unroll
                for (int ni = 0; ni < 8; ni++) {
                    int col = wn * 64 + ni * 8 + c2;
                    float2 v = make_float2(acc[mi][ni][jh * 2 + 0], acc[mi][ni][jh * 2 + 1]);
                    *(float2*)(Cp + col) = v;
                }
            }
        }
    }
}

// ---------------------------------------------------------------------------
// dual_gemm: C = A1@B1 (+ A2@B2) + bias   (grid: 313) — h embed and h_new
// ---------------------------------------------------------------------------
__global__ __launch_bounds__(GT, 1)
void dual_gemm(const float* __restrict__ A1, int slot1,
               const float* __restrict__ A2, int slot2,
               const float* __restrict__ bias, float* __restrict__ C)
{
    extern __shared__ char smem[];
    uint32_t sb = smem_u32(smem);
    const int tid = threadIdx.x, wid = tid >> 5, lane = tid & 31;
    const int m0 = blockIdx.x * 128;
    const int wm = wid & 3, wn = wid >> 2;
    const int r4 = lane >> 2, c2 = (lane & 3) * 2;

    stage_A<true>(A1, m0, N_NODES, tid, smem);
    stage_B(slot1, tid, smem);
    __syncthreads();
    float acc[2][8][4];
    mma_tile(sb, wid, lane, acc, true);

    if (A2) {
        __syncthreads();                    // all warps done reading smem
        stage_A<true>(A2, m0, N_NODES, tid, smem);
        stage_B(slot2, tid, smem);
        __syncthreads();
        mma_tile(sb, wid, lane, acc, false);
    }

#pragma unroll
    for (int mi = 0; mi < 2; mi++) {
#pragma unroll
        for (int jh = 0; jh < 2; jh++) {
            int row = m0 + wm * 32 + mi * 16 + jh * 8 + r4;
            if (row >= N_NODES) continue;
            float* Cp = C + (size_t)row * HID;
#pragma unroll
            for (int ni = 0; ni < 8; ni++) {
                int col = wn * 64 + ni * 8 + c2;
                float2 b = *(const float2*)(bias + col);
                float2 v = make_float2(acc[mi][ni][jh * 2 + 0] + b.x,
                                       acc[mi][ni][jh * 2 + 1] + b.y);
                *(float2*)(Cp + col) = v;
            }
        }
    }
}

// ---------------------------------------------------------------------------
// edge_gemm: grid (5000). One CTA stages the e-tile once and does BOTH:
//   msg = e@Wm_e + bm + P[s,0:128] + P[r,128:256]  -> red.add agg[r]
//   e'  = e@We_e + be + P[s,256:384] + P[r,384:512] -> e_out
// ---------------------------------------------------------------------------
__global__ __launch_bounds__(GT, 1)
void edge_gemm(const float* __restrict__ E_in, int slot_m, int slot_e,
               const float* __restrict__ bm, const float* __restrict__ be,
               const float* __restrict__ P,
               const int* __restrict__ send, const int* __restrict__ rec,
               float* __restrict__ agg, float* __restrict__ e_out)
{
    extern __shared__ char smem[];
    uint32_t sb = smem_u32(smem);
    const int tid = threadIdx.x, wid = tid >> 5, lane = tid & 31;
    const int m0 = blockIdx.x * 128;
    const int wm = wid & 3, wn = wid >> 2;
    const int r4 = lane >> 2, c2 = (lane & 3) * 2;

    stage_A<false>(E_in, m0, N_EDGES, tid, smem);
    stage_B(slot_m, tid, smem);
    __syncthreads();
    float acc[2][8][4];
    mma_tile(sb, wid, lane, acc, true);

    // ---- message path: red.add into agg[rec] ----
#pragma unroll
    for (int mi = 0; mi < 2; mi++) {
#pragma unroll
        for (int jh = 0; jh < 2; jh++) {
            int row = m0 + wm * 32 + mi * 16 + jh * 8 + r4;
            int s = send[row], r = rec[row];
            const float* Ps = P + (size_t)s * 512;
            const float* Pr = P + (size_t)r * 512 + 128;
            float* ap = agg + (size_t)r * HID;
#pragma unroll
            for (int ni = 0; ni < 8; ni++) {
                int col = wn * 64 + ni * 8 + c2;
                float2 b = *(const float2*)(bm + col);
                float2 p = *(const float2*)(Ps + col);
                float2 q = *(const float2*)(Pr + col);
                red_add_v2(ap + col,
                           acc[mi][ni][jh * 2 + 0] + b.x + p.x + q.x,
                           acc[mi][ni][jh * 2 + 1] + b.y + p.y + q.y);
            }
        }
    }

    // ---- edge-update path: reuse staged A, swap in We_e ----
    __syncthreads();
    stage_B(slot_e, tid, smem);
    __syncthreads();
    mma_tile(sb, wid, lane, acc, true);

#pragma unroll
    for (int mi = 0; mi < 2; mi++) {
#pragma unroll
        for (int jh = 0; jh < 2; jh++) {
            int row = m0 + wm * 32 + mi * 16 + jh * 8 + r4;
            int s = send[row], r = rec[row];
            const float* Ps = P + (size_t)s * 512 + 256;
            const float* Pr = P + (size_t)r * 512 + 384;
            float* op = e_out + (size_t)row * HID;
#pragma unroll
            for (int ni = 0; ni < 8; ni++) {
                int col = wn * 64 + ni * 8 + c2;
                float2 b = *(const float2*)(be + col);
                float2 p = *(const float2*)(Ps + col);
                float2 q = *(const float2*)(Pr + col);
                float2 v = make_float2(acc[mi][ni][jh * 2 + 0] + b.x + p.x + q.x,
                                       acc[mi][ni][jh * 2 + 1] + b.y + p.y + q.y);
                *(float2*)(op + col) = v;
            }
        }
    }
}

// ---------------------------------------------------------------------------
// Edge embedding: e0 = E[:,0:16] @ W[16,128] + b
// ---------------------------------------------------------------------------
__global__ __launch_bounds__(128)
void embed_e_kernel(const float* __restrict__ e_in, const float* __restrict__ W,
                    const float* __restrict__ b, float* __restrict__ out)
{
    __shared__ float Ws[16 * 128];
    __shared__ float bs[128];
    for (int i = threadIdx.x; i < 16 * 128; i += blockDim.x) Ws[i] = W[i];
    if (threadIdx.x < 128) bs[threadIdx.x] = b[threadIdx.x];
    __syncthreads();
    const int c = threadIdx.x;
    for (int k = blockIdx.x; k < N_EDGES; k += gridDim.x) {
        const float* er = e_in + (size_t)k * 16;
        float acc = bs[c];
#pragma unroll
        for (int j = 0; j < 16; j++) acc += er[j] * Ws[j * 128 + c];
        out[(size_t)k * HID + c] = acc;
    }
}

__global__ __launch_bounds__(128)
void pool_kernel(const float* __restrict__ h, const int* __restrict__ batch,
                 float* __restrict__ out)
{
    const int n = blockIdx.x;
    const int c = threadIdx.x;
    const int g = batch[n];
    atomicAdd(&out[(size_t)g * HID + c], h[(size_t)n * HID + c]);
}

// ---------------------------------------------------------------------------
// Launch
// ---------------------------------------------------------------------------
extern "C" void kernel_launch(void* const* d_in, const int* in_sizes, int n_in,
                              void* d_out, int out_size)
{
    const float* h_in     = (const float*)d_in[0];
    const float* e_in     = (const float*)d_in[1];
    const int*   edge_idx = (const int*)  d_in[2];
    const int*   batch    = (const int*)  d_in[3];
    const float* W_embed  = (const float*)d_in[4];
    const float* b_embed  = (const float*)d_in[5];
    const float* W_eembed = (const float*)d_in[6];
    const float* b_eembed = (const float*)d_in[7];
    const float* Wm       = (const float*)d_in[8];
    const float* bm       = (const float*)d_in[9];
    const float* Wh       = (const float*)d_in[10];
    const float* bh       = (const float*)d_in[11];
    const float* We       = (const float*)d_in[12];
    const float* be       = (const float*)d_in[13];
    float*       out      = (float*)d_out;

    cudaFuncSetAttribute(proj_gemm, cudaFuncAttributeMaxDynamicSharedMemorySize, SMEM_SZ);
    cudaFuncSetAttribute(dual_gemm, cudaFuncAttributeMaxDynamicSharedMemorySize, SMEM_SZ);
    cudaFuncSetAttribute(edge_gemm, cudaFuncAttributeMaxDynamicSharedMemorySize, SMEM_SZ);

    float *hbuf, *ebuf, *Pp, *aggp;
    cudaGetSymbolAddress((void**)&hbuf, g_h);
    cudaGetSymbolAddress((void**)&ebuf, g_e);
    cudaGetSymbolAddress((void**)&Pp,   g_P);
    cudaGetSymbolAddress((void**)&aggp, g_agg);

    float* hb[2] = { hbuf, hbuf + (size_t)N_NODES * HID };
    float* eb[2] = { ebuf, ebuf + (size_t)N_EDGES * HID };
    const int* send = edge_idx;
    const int* rec  = edge_idx + N_EDGES;

    // Weight prep + embeddings
    prep_weights<<<33, 256>>>(W_embed, Wm, Wh, We);
    embed_e_kernel<<<2048, 128>>>(e_in, W_eembed, b_eembed, eb[0]);
    dual_gemm<<<NODE_TILES, GT, SMEM_SZ>>>(h_in, 0, nullptr, 0, b_embed, hb[0]);

    int cur = 0;
    for (int l = 0; l < N_LAYERS; l++) {
        int sbase = 1 + l * 8;
        const float* bm_l = bm + (size_t)l * HID;
        const float* bh_l = bh + (size_t)l * HID;
        const float* be_l = be + (size_t)l * HID;
        float* hcur = hb[cur];
        float* ecur = eb[cur];
        float* hnxt = hb[1 - cur];
        float* enxt = eb[1 - cur];

        // P = h @ [Wm_s | Wm_r | We_s | We_r]  -> [N, 512]
        proj_gemm<<<NODE_TILES, GT, SMEM_SZ>>>(hcur, sbase, Pp);

        cudaMemsetAsync(aggp, 0, (size_t)N_NODES * HID * sizeof(float));

        // Fused edge GEMMs (message + scatter-add, then edge update) — e staged once
        edge_gemm<<<EDGE_TILES, GT, SMEM_SZ>>>(
            ecur, sbase + 2, sbase + 5, bm_l, be_l, Pp, send, rec, aggp, enxt);

        // h_new = [h | agg] @ Wh + bh
        dual_gemm<<<NODE_TILES, GT, SMEM_SZ>>>(hcur, sbase + 6, aggp, sbase + 7, bh_l, hnxt);

        cur = 1 - cur;
    }

    cudaMemsetAsync(d_out, 0, (size_t)NUM_GRAPHS * HID * sizeof(float));
    pool_kernel<<<N_NODES, 128>>>(hb[cur], batch, out);
}

// round 5
// speedup vs baseline: 1.9458x; 1.1262x over previous
#include <cuda_runtime.h>
#include <cuda_bf16.h>
#include <cstdint>

#define N_NODES 40000
#define N_PAD   40064   // 313 * 128
#define N_EDGES 640000
#define HID 128
#define N_LAYERS 4
#define NUM_GRAPHS 256

#define GT 256          // 8 warps per GEMM CTA
#define NODE_TILES 313  // N_PAD / 128
#define EDGE_TILES 5000 // 640000/128

// B tile in SMEM: padded row-major [n][k] bf16, 128 rows x 272B; hi at 0, lo at +TILE_BYTES
#define LDB 272
#define TILE_BYTES 34816
#define SMEM_SZ 69632   // hi + lo  -> 2 CTAs/SM

// ---------------------------------------------------------------------------
// Scratch (padded row counts)
// ---------------------------------------------------------------------------
__device__ float g_h[2][(size_t)N_PAD * HID];
__device__ float g_e[2][(size_t)N_EDGES * HID];
__device__ float g_P[(size_t)N_PAD * 4 * HID];     // [N,512]: hWm_s | hWm_r | hWe_s | hWe_r
__device__ float g_agg[(size_t)N_PAD * HID];
// 33 weight slots: each = hi image (34816 B) + lo image (34816 B), padded [n][k]
__device__ uint4 g_Bw[(size_t)33 * 4352];

// ---------------------------------------------------------------------------
// PTX helpers (baseline ISA only)
// ---------------------------------------------------------------------------
__device__ __forceinline__ uint32_t smem_u32(const void* p) {
    uint32_t a;
    asm("{ .reg .u64 t; cvta.to.shared.u64 t, %1; cvt.u32.u64 %0, t; }" : "=r"(a) : "l"(p));
    return a;
}
__device__ __forceinline__ void red_add_v2(float* addr, float a, float b) {
    asm volatile("red.global.add.v2.f32 [%0], {%1, %2};"
                 :: "l"(addr), "f"(a), "f"(b) : "memory");
}
__device__ __forceinline__ void ldsm_x4(uint32_t addr, uint32_t r[4]) {
    asm volatile("ldmatrix.sync.aligned.m8n8.x4.shared.b16 {%0,%1,%2,%3}, [%4];"
                 : "=r"(r[0]), "=r"(r[1]), "=r"(r[2]), "=r"(r[3]) : "r"(addr));
}
__device__ __forceinline__ void mma_bf16(float c[4], const uint32_t a[4], uint32_t b0, uint32_t b1) {
    asm volatile("mma.sync.aligned.m16n8k16.row.col.f32.bf16.bf16.f32 "
                 "{%0,%1,%2,%3}, {%4,%5,%6,%7}, {%8,%9}, {%0,%1,%2,%3};"
                 : "+f"(c[0]), "+f"(c[1]), "+f"(c[2]), "+f"(c[3])
                 : "r"(a[0]), "r"(a[1]), "r"(a[2]), "r"(a[3]), "r"(b0), "r"(b1));
}
__device__ __forceinline__ uint32_t pack_hi_lo(float a, float b, uint32_t& lo_out) {
    __nv_bfloat16 ha = __float2bfloat16_rn(a), hb = __float2bfloat16_rn(b);
    float ra = a - __bfloat162float(ha), rb = b - __bfloat162float(hb);
    __nv_bfloat16 la = __float2bfloat16_rn(ra), lb = __float2bfloat16_rn(rb);
    lo_out = (uint32_t)__bfloat16_as_ushort(la) | ((uint32_t)__bfloat16_as_ushort(lb) << 16);
    return (uint32_t)__bfloat16_as_ushort(ha) | ((uint32_t)__bfloat16_as_ushort(hb) << 16);
}

// Stage B: copy pre-split hi+lo images (69632 B) from g_Bw slot into SMEM
__device__ __forceinline__ void stage_B(int slot, int tid, char* smem)
{
    const uint4* src = g_Bw + (size_t)slot * 4352;
    uint4* dst = (uint4*)smem;
#pragma unroll
    for (int i = 0; i < 17; i++) dst[tid + i * 256] = src[tid + i * 256];
}

// ---------------------------------------------------------------------------
// A fragments (m16k16, rows row0..row0+31 for this warp) straight from gmem,
// converted to bf16 hi/lo in registers. GUARD clamps rows >= N_NODES (h_in only).
// ---------------------------------------------------------------------------
template<bool GUARD>
__device__ __forceinline__ void load_A_ks(const float* __restrict__ A, int row0, int k0,
                                          int lane, uint32_t hi[8], uint32_t lo[8])
{
    const int r = row0 + (lane >> 2);
    const int c = k0 + (lane & 3) * 2;
#pragma unroll
    for (int mi = 0; mi < 2; mi++) {
#pragma unroll
        for (int p = 0; p < 4; p++) {
            int row = r + mi * 16 + (p & 1) * 8;
            int col = c + (p >> 1) * 8;
            float2 v = make_float2(0.f, 0.f);
            if (!GUARD || row < N_NODES)
                v = *(const float2*)(A + (size_t)row * HID + col);
            hi[mi * 4 + p] = pack_hi_lo(v.x, v.y, lo[mi * 4 + p]);
        }
    }
}

// ---------------------------------------------------------------------------
// Full K=128 pass: 3-product bf16 emulation, acc[mi][ni][4]; warp = 32x64 region
// B (hi/lo) comes from SMEM via ldmatrix; A comes from gmem via load_A_ks.
// ---------------------------------------------------------------------------
template<bool GUARD>
__device__ __forceinline__ void mma_pass(const float* __restrict__ A, int m0,
                                         uint32_t sb, int wid, int lane,
                                         float acc[2][8][4])
{
    const int wm = wid & 3, wn = wid >> 2;
    const uint32_t lrow = (uint32_t)((lane & 15) * LDB + (lane >> 4) * 16);
    const uint32_t bBase = sb + wn * 64 * LDB + lrow;
    const int row0 = m0 + wm * 32;

#pragma unroll
    for (int ks = 0; ks < 8; ks++) {
        uint32_t ah[8], al[8];
        load_A_ks<GUARD>(A, row0, ks * 16, lane, ah, al);
        const uint32_t ko = ks * 32;
#pragma unroll
        for (int nb = 0; nb < 4; nb++) {
            uint32_t bh[4], bl[4];
            ldsm_x4(bBase + nb * 16 * LDB + ko, bh);
            ldsm_x4(bBase + nb * 16 * LDB + ko + TILE_BYTES, bl);
#pragma unroll
            for (int half = 0; half < 2; half++) {
                const int ni = nb * 2 + half;
#pragma unroll
                for (int mi = 0; mi < 2; mi++) {
                    mma_bf16(acc[mi][ni], &ah[mi * 4], bh[half], bh[half + 2]);
                    mma_bf16(acc[mi][ni], &ah[mi * 4], bl[half], bl[half + 2]);
                    mma_bf16(acc[mi][ni], &al[mi * 4], bh[half], bh[half + 2]);
                }
            }
        }
    }
}

__device__ __forceinline__ void zero_acc(float acc[2][8][4]) {
#pragma unroll
    for (int mi = 0; mi < 2; mi++)
#pragma unroll
        for (int ni = 0; ni < 8; ni++)
#pragma unroll
            for (int j = 0; j < 4; j++) acc[mi][ni][j] = 0.f;
}

// ---------------------------------------------------------------------------
// Weight prep: 33 fp32 [K=128][N=128] blocks -> bf16 hi/lo padded [n][k] images
// slots: 0 = W_embed; per layer l: 1+8l+{0..2}=Wm{s,r,e}, {3..5}=We{s,r,e}, {6,7}=Wh{a,b}
// ---------------------------------------------------------------------------
__global__ __launch_bounds__(256)
void prep_weights(const float* __restrict__ W_embed, const float* __restrict__ Wm,
                  const float* __restrict__ Wh, const float* __restrict__ We)
{
    int t = blockIdx.x;
    const float* src;
    if (t == 0) src = W_embed;
    else {
        int tt = t - 1, l = tt >> 3, j = tt & 7;
        if (j < 3)      src = Wm + (size_t)l * 384 * HID + j * 16384;
        else if (j < 6) src = We + (size_t)l * 384 * HID + (j - 3) * 16384;
        else            src = Wh + (size_t)l * 256 * HID + (j - 6) * 16384;
    }
    char* dst = (char*)(g_Bw + (size_t)t * 4352);
    for (int i = threadIdx.x; i < 16384; i += 256) {
        int k = i >> 7, n = i & 127;
        float v = src[i];
        __nv_bfloat16 h = __float2bfloat16_rn(v);
        __nv_bfloat16 lo = __float2bfloat16_rn(v - __bfloat162float(h));
        uint32_t off = (uint32_t)(n * LDB + k * 2);
        *(__nv_bfloat16*)(dst + off) = h;
        *(__nv_bfloat16*)(dst + TILE_BYTES + off) = lo;
    }
}

// ---------------------------------------------------------------------------
// proj_gemm: grid (4, 313). P[:, y*128:(y+1)*128] = h @ Wblock[y]
// ---------------------------------------------------------------------------
__global__ __launch_bounds__(GT, 2)
void proj_gemm(const float* __restrict__ A, int sbase, float* __restrict__ C)
{
    extern __shared__ char smem[];
    uint32_t sb = smem_u32(smem);
    const int tid = threadIdx.x, wid = tid >> 5, lane = tid & 31;
    const int y = blockIdx.x;
    const int m0 = blockIdx.y * 128;
    const int wm = wid & 3, wn = wid >> 2;
    const int r4 = lane >> 2, c2 = (lane & 3) * 2;

    stage_B(sbase + ((y < 2) ? y : y + 1), tid, smem);
    __syncthreads();

    float acc[2][8][4];
    zero_acc(acc);
    mma_pass<false>(A, m0, sb, wid, lane, acc);

#pragma unroll
    for (int mi = 0; mi < 2; mi++) {
#pragma unroll
        for (int jh = 0; jh < 2; jh++) {
            int row = m0 + wm * 32 + mi * 16 + jh * 8 + r4;
            float* Cp = C + (size_t)row * 512 + y * 128;
#pragma unroll
            for (int ni = 0; ni < 8; ni++) {
                int col = wn * 64 + ni * 8 + c2;
                *(float2*)(Cp + col) = make_float2(acc[mi][ni][jh * 2 + 0],
                                                   acc[mi][ni][jh * 2 + 1]);
            }
        }
    }
}

// ---------------------------------------------------------------------------
// dual_gemm: C = A1@B1 (+ A2@B2) + bias  (grid: 313) — h embed (GUARD) and h_new
// ---------------------------------------------------------------------------
template<bool GUARD>
__global__ __launch_bounds__(GT, 2)
void dual_gemm(const float* __restrict__ A1, int slot1,
               const float* __restrict__ A2, int slot2,
               const float* __restrict__ bias, float* __restrict__ C)
{
    extern __shared__ char smem[];
    uint32_t sb = smem_u32(smem);
    const int tid = threadIdx.x, wid = tid >> 5, lane = tid & 31;
    const int m0 = blockIdx.x * 128;
    const int wm = wid & 3, wn = wid >> 2;
    const int r4 = lane >> 2, c2 = (lane & 3) * 2;

    stage_B(slot1, tid, smem);
    __syncthreads();
    float acc[2][8][4];
    zero_acc(acc);
    mma_pass<GUARD>(A1, m0, sb, wid, lane, acc);

    if (A2) {
        __syncthreads();                    // all warps done with B1
        stage_B(slot2, tid, smem);
        __syncthreads();
        mma_pass<false>(A2, m0, sb, wid, lane, acc);
    }

#pragma unroll
    for (int mi = 0; mi < 2; mi++) {
#pragma unroll
        for (int jh = 0; jh < 2; jh++) {
            int row = m0 + wm * 32 + mi * 16 + jh * 8 + r4;
            float* Cp = C + (size_t)row * HID;
#pragma unroll
            for (int ni = 0; ni < 8; ni++) {
                int col = wn * 64 + ni * 8 + c2;
                float2 b = *(const float2*)(bias + col);
                *(float2*)(Cp + col) = make_float2(acc[mi][ni][jh * 2 + 0] + b.x,
                                                   acc[mi][ni][jh * 2 + 1] + b.y);
            }
        }
    }
}

// ---------------------------------------------------------------------------
// edge_gemm: grid (2, 5000)
//  x==0: msg = e@Wm_e + bm + P[s,0:128] + P[r,128:256]  -> red.add agg[r]
//  x==1: e'  = e@We_e + be + P[s,256:384] + P[r,384:512] -> e_out
// ---------------------------------------------------------------------------
__global__ __launch_bounds__(GT, 2)
void edge_gemm(const float* __restrict__ E_in, int slot_m, int slot_e,
               const float* __restrict__ bm, const float* __restrict__ be,
               const float* __restrict__ P,
               const int* __restrict__ send, const int* __restrict__ rec,
               float* __restrict__ agg, float* __restrict__ e_out)
{
    extern __shared__ char smem[];
    uint32_t sb = smem_u32(smem);
    const int tid = threadIdx.x, wid = tid >> 5, lane = tid & 31;
    const int which = blockIdx.x;
    const int m0 = blockIdx.y * 128;
    const int wm = wid & 3, wn = wid >> 2;
    const int r4 = lane >> 2, c2 = (lane & 3) * 2;

    stage_B(which ? slot_e : slot_m, tid, smem);
    __syncthreads();

    float acc[2][8][4];
    zero_acc(acc);
    mma_pass<false>(E_in, m0, sb, wid, lane, acc);

    if (which == 0) {
#pragma unroll
        for (int mi = 0; mi < 2; mi++) {
#pragma unroll
            for (int jh = 0; jh < 2; jh++) {
                int row = m0 + wm * 32 + mi * 16 + jh * 8 + r4;
                int s = send[row], r = rec[row];
                const float* Ps = P + (size_t)s * 512;
                const float* Pr = P + (size_t)r * 512 + 128;
                float* ap = agg + (size_t)r * HID;
#pragma unroll
                for (int ni = 0; ni < 8; ni++) {
                    int col = wn * 64 + ni * 8 + c2;
                    float2 b = *(const float2*)(bm + col);
                    float2 p = *(const float2*)(Ps + col);
                    float2 q = *(const float2*)(Pr + col);
                    red_add_v2(ap + col,
                               acc[mi][ni][jh * 2 + 0] + b.x + p.x + q.x,
                               acc[mi][ni][jh * 2 + 1] + b.y + p.y + q.y);
                }
            }
        }
    } else {
#pragma unroll
        for (int mi = 0; mi < 2; mi++) {
#pragma unroll
            for (int jh = 0; jh < 2; jh++) {
                int row = m0 + wm * 32 + mi * 16 + jh * 8 + r4;
                int s = send[row], r = rec[row];
                const float* Ps = P + (size_t)s * 512 + 256;
                const float* Pr = P + (size_t)r * 512 + 384;
                float* op = e_out + (size_t)row * HID;
#pragma unroll
                for (int ni = 0; ni < 8; ni++) {
                    int col = wn * 64 + ni * 8 + c2;
                    float2 b = *(const float2*)(be + col);
                    float2 p = *(const float2*)(Ps + col);
                    float2 q = *(const float2*)(Pr + col);
                    *(float2*)(op + col) = make_float2(
                        acc[mi][ni][jh * 2 + 0] + b.x + p.x + q.x,
                        acc[mi][ni][jh * 2 + 1] + b.y + p.y + q.y);
                }
            }
        }
    }
}

// ---------------------------------------------------------------------------
// Edge embedding: e0 = E[:,0:16] @ W[16,128] + b
// ---------------------------------------------------------------------------
__global__ __launch_bounds__(128)
void embed_e_kernel(const float* __restrict__ e_in, const float* __restrict__ W,
                    const float* __restrict__ b, float* __restrict__ out)
{
    __shared__ float Ws[16 * 128];
    __shared__ float bs[128];
    for (int i = threadIdx.x; i < 16 * 128; i += blockDim.x) Ws[i] = W[i];
    if (threadIdx.x < 128) bs[threadIdx.x] = b[threadIdx.x];
    __syncthreads();
    const int c = threadIdx.x;
    for (int k = blockIdx.x; k < N_EDGES; k += gridDim.x) {
        const float* er = e_in + (size_t)k * 16;
        float acc = bs[c];
#pragma unroll
        for (int j = 0; j < 16; j++) acc += er[j] * Ws[j * 128 + c];
        out[(size_t)k * HID + c] = acc;
    }
}

__global__ __launch_bounds__(128)
void pool_kernel(const float* __restrict__ h, const int* __restrict__ batch,
                 float* __restrict__ out)
{
    const int n = blockIdx.x;
    const int c = threadIdx.x;
    const int g = batch[n];
    atomicAdd(&out[(size_t)g * HID + c], h[(size_t)n * HID + c]);
}

// ---------------------------------------------------------------------------
// Launch
// ---------------------------------------------------------------------------
extern "C" void kernel_launch(void* const* d_in, const int* in_sizes, int n_in,
                              void* d_out, int out_size)
{
    const float* h_in     = (const float*)d_in[0];
    const float* e_in     = (const float*)d_in[1];
    const int*   edge_idx = (const int*)  d_in[2];
    const int*   batch    = (const int*)  d_in[3];
    const float* W_embed  = (const float*)d_in[4];
    const float* b_embed  = (const float*)d_in[5];
    const float* W_eembed = (const float*)d_in[6];
    const float* b_eembed = (const float*)d_in[7];
    const float* Wm       = (const float*)d_in[8];
    const float* bm       = (const float*)d_in[9];
    const float* Wh       = (const float*)d_in[10];
    const float* bh       = (const float*)d_in[11];
    const float* We       = (const float*)d_in[12];
    const float* be       = (const float*)d_in[13];
    float*       out      = (float*)d_out;

    cudaFuncSetAttribute(proj_gemm,        cudaFuncAttributeMaxDynamicSharedMemorySize, SMEM_SZ);
    cudaFuncSetAttribute(dual_gemm<true>,  cudaFuncAttributeMaxDynamicSharedMemorySize, SMEM_SZ);
    cudaFuncSetAttribute(dual_gemm<false>, cudaFuncAttributeMaxDynamicSharedMemorySize, SMEM_SZ);
    cudaFuncSetAttribute(edge_gemm,        cudaFuncAttributeMaxDynamicSharedMemorySize, SMEM_SZ);

    float *hbuf, *ebuf, *Pp, *aggp;
    cudaGetSymbolAddress((void**)&hbuf, g_h);
    cudaGetSymbolAddress((void**)&ebuf, g_e);
    cudaGetSymbolAddress((void**)&Pp,   g_P);
    cudaGetSymbolAddress((void**)&aggp, g_agg);

    float* hb[2] = { hbuf, hbuf + (size_t)N_PAD * HID };
    float* eb[2] = { ebuf, ebuf + (size_t)N_EDGES * HID };
    const int* send = edge_idx;
    const int* rec  = edge_idx + N_EDGES;

    // Weight prep + embeddings
    prep_weights<<<33, 256>>>(W_embed, Wm, Wh, We);
    embed_e_kernel<<<2048, 128>>>(e_in, W_eembed, b_eembed, eb[0]);
    dual_gemm<true><<<NODE_TILES, GT, SMEM_SZ>>>(h_in, 0, nullptr, 0, b_embed, hb[0]);

    int cur = 0;
    for (int l = 0; l < N_LAYERS; l++) {
        int sbase = 1 + l * 8;
        const float* bm_l = bm + (size_t)l * HID;
        const float* bh_l = bh + (size_t)l * HID;
        const float* be_l = be + (size_t)l * HID;
        float* hcur = hb[cur];
        float* ecur = eb[cur];
        float* hnxt = hb[1 - cur];
        float* enxt = eb[1 - cur];

        // P = h @ [Wm_s | Wm_r | We_s | We_r]  -> [N, 512]
        proj_gemm<<<dim3(4, NODE_TILES), GT, SMEM_SZ>>>(hcur, sbase, Pp);

        cudaMemsetAsync(aggp, 0, (size_t)N_PAD * HID * sizeof(float));

        // Fused edge GEMMs: x=0 message+scatter, x=1 edge update
        edge_gemm<<<dim3(2, EDGE_TILES), GT, SMEM_SZ>>>(
            ecur, sbase + 2, sbase + 5, bm_l, be_l, Pp, send, rec, aggp, enxt);

        // h_new = [h | agg] @ Wh + bh
        dual_gemm<false><<<NODE_TILES, GT, SMEM_SZ>>>(hcur, sbase + 6, aggp, sbase + 7, bh_l, hnxt);

        cur = 1 - cur;
    }

    cudaMemsetAsync(d_out, 0, (size_t)NUM_GRAPHS * HID * sizeof(float));
    pool_kernel<<<N_NODES, 128>>>(hb[cur], batch, out);
}

// round 6
// speedup vs baseline: 1.9790x; 1.0171x over previous
#include <cuda_runtime.h>
#include <cuda_bf16.h>
#include <cstdint>

#define N_NODES 40000
#define N_PAD   40064   // 313 * 128
#define N_EDGES 640000
#define HID 128
#define N_LAYERS 4
#define NUM_GRAPHS 256

#define GT 256          // 8 warps per GEMM CTA
#define NODE_TILES 313  // N_PAD / 128
#define EDGE_TILES 5000 // 640000/128

// B tile in SMEM: padded row-major [n][k] bf16, 128 rows x 272B; hi at 0, lo at +TILE_BYTES
#define LDB 272
#define TILE_BYTES 34816
#define SMEM_SZ 69632   // hi + lo  -> 2 CTAs/SM

// ---------------------------------------------------------------------------
// Scratch (padded row counts)
// ---------------------------------------------------------------------------
__device__ float g_h[2][(size_t)N_PAD * HID];
__device__ float g_e[2][(size_t)N_EDGES * HID];
__device__ float g_P[(size_t)N_PAD * 4 * HID];     // [N,512]: hWm_s | hWm_r | hWe_s | hWe_r
__device__ float g_agg[(size_t)N_PAD * HID];
// 33 weight slots: each = hi image (34816 B) + lo image (34816 B), padded [n][k]
__device__ uint4 g_Bw[(size_t)33 * 4352];

// ---------------------------------------------------------------------------
// PTX helpers (baseline ISA only)
// ---------------------------------------------------------------------------
__device__ __forceinline__ uint32_t smem_u32(const void* p) {
    uint32_t a;
    asm("{ .reg .u64 t; cvta.to.shared.u64 t, %1; cvt.u32.u64 %0, t; }" : "=r"(a) : "l"(p));
    return a;
}
__device__ __forceinline__ void red_add_v2(float* addr, float a, float b) {
    asm volatile("red.global.add.v2.f32 [%0], {%1, %2};"
                 :: "l"(addr), "f"(a), "f"(b) : "memory");
}
__device__ __forceinline__ void ldsm_x4(uint32_t addr, uint32_t r[4]) {
    asm volatile("ldmatrix.sync.aligned.m8n8.x4.shared.b16 {%0,%1,%2,%3}, [%4];"
                 : "=r"(r[0]), "=r"(r[1]), "=r"(r[2]), "=r"(r[3]) : "r"(addr));
}
__device__ __forceinline__ void mma_bf16(float c[4], const uint32_t a[4], uint32_t b0, uint32_t b1) {
    asm volatile("mma.sync.aligned.m16n8k16.row.col.f32.bf16.bf16.f32 "
                 "{%0,%1,%2,%3}, {%4,%5,%6,%7}, {%8,%9}, {%0,%1,%2,%3};"
                 : "+f"(c[0]), "+f"(c[1]), "+f"(c[2]), "+f"(c[3])
                 : "r"(a[0]), "r"(a[1]), "r"(a[2]), "r"(a[3]), "r"(b0), "r"(b1));
}
__device__ __forceinline__ uint32_t pack_hi_lo(float a, float b, uint32_t& lo_out) {
    __nv_bfloat16 ha = __float2bfloat16_rn(a), hb = __float2bfloat16_rn(b);
    float ra = a - __bfloat162float(ha), rb = b - __bfloat162float(hb);
    __nv_bfloat16 la = __float2bfloat16_rn(ra), lb = __float2bfloat16_rn(rb);
    lo_out = (uint32_t)__bfloat16_as_ushort(la) | ((uint32_t)__bfloat16_as_ushort(lb) << 16);
    return (uint32_t)__bfloat16_as_ushort(ha) | ((uint32_t)__bfloat16_as_ushort(hb) << 16);
}

// Stage B: copy pre-split hi+lo images (69632 B) from g_Bw slot into SMEM
__device__ __forceinline__ void stage_B(int slot, int tid, char* smem)
{
    const uint4* src = g_Bw + (size_t)slot * 4352;
    uint4* dst = (uint4*)smem;
#pragma unroll
    for (int i = 0; i < 17; i++) dst[tid + i * 256] = src[tid + i * 256];
}

// ---------------------------------------------------------------------------
// Raw A fragment slice for one ks (K=16): 8 float2 per lane.
// av[mi*4 + jh + 2*jc] = A[row0 + mi*16 + jh*8 + (lane>>2)][k0 + (lane&3)*2 + jc*8]
// ---------------------------------------------------------------------------
template<bool GUARD>
__device__ __forceinline__ void load_A_raw(const float* __restrict__ A, int row0, int k0,
                                           int lane, float2 av[8])
{
    const int r = row0 + (lane >> 2);
    const int c = k0 + (lane & 3) * 2;
#pragma unroll
    for (int mi = 0; mi < 2; mi++) {
#pragma unroll
        for (int jh = 0; jh < 2; jh++) {
            int row = r + mi * 16 + jh * 8;
            const float* rp = A + (size_t)row * HID + c;
#pragma unroll
            for (int jc = 0; jc < 2; jc++) {
                float2 v = make_float2(0.f, 0.f);
                if (!GUARD || row < N_NODES) v = *(const float2*)(rp + jc * 8);
                av[mi * 4 + jh + 2 * jc] = v;
            }
        }
    }
}

// ---------------------------------------------------------------------------
// Full K=128 pass, software-pipelined A prefetch:
// 3-product bf16 emulation, acc[mi][ni][4]; warp = 32x64 region of 128x128 tile
// ---------------------------------------------------------------------------
template<bool GUARD>
__device__ __forceinline__ void mma_pass(const float* __restrict__ A, int m0,
                                         uint32_t sb, int wid, int lane,
                                         float acc[2][8][4])
{
    const int wm = wid & 3, wn = wid >> 2;
    const uint32_t lrow = (uint32_t)((lane & 15) * LDB + (lane >> 4) * 16);
    const uint32_t bBase = sb + wn * 64 * LDB + lrow;
    const int row0 = m0 + wm * 32;

    float2 av[8];
    load_A_raw<GUARD>(A, row0, 0, lane, av);

#pragma unroll
    for (int ks = 0; ks < 8; ks++) {
        // convert current slice to hi/lo bf16 fragments
        uint32_t ah[8], al[8];
#pragma unroll
        for (int i = 0; i < 8; i++) ah[i] = pack_hi_lo(av[i].x, av[i].y, al[i]);
        // prefetch next slice while MMAs run
        if (ks < 7) load_A_raw<GUARD>(A, row0, (ks + 1) * 16, lane, av);

        const uint32_t ko = (uint32_t)(ks * 32);
#pragma unroll
        for (int nb = 0; nb < 4; nb++) {
            uint32_t bh[4], bl[4];
            ldsm_x4(bBase + nb * 16 * LDB + ko, bh);
            ldsm_x4(bBase + nb * 16 * LDB + ko + TILE_BYTES, bl);
#pragma unroll
            for (int half = 0; half < 2; half++) {
                const int ni = nb * 2 + half;
#pragma unroll
                for (int mi = 0; mi < 2; mi++) {
                    mma_bf16(acc[mi][ni], &ah[mi * 4], bh[half], bh[half + 2]);
                    mma_bf16(acc[mi][ni], &ah[mi * 4], bl[half], bl[half + 2]);
                    mma_bf16(acc[mi][ni], &al[mi * 4], bh[half], bh[half + 2]);
                }
            }
        }
    }
}

__device__ __forceinline__ void zero_acc(float acc[2][8][4]) {
#pragma unroll
    for (int mi = 0; mi < 2; mi++)
#pragma unroll
        for (int ni = 0; ni < 8; ni++)
#pragma unroll
            for (int j = 0; j < 4; j++) acc[mi][ni][j] = 0.f;
}

// ---------------------------------------------------------------------------
// Weight prep: 33 fp32 [K=128][N=128] blocks -> bf16 hi/lo padded [n][k] images
// slots: 0 = W_embed; per layer l: 1+8l+{0..2}=Wm{s,r,e}, {3..5}=We{s,r,e}, {6,7}=Wh{a,b}
// ---------------------------------------------------------------------------
__global__ __launch_bounds__(256)
void prep_weights(const float* __restrict__ W_embed, const float* __restrict__ Wm,
                  const float* __restrict__ Wh, const float* __restrict__ We)
{
    int t = blockIdx.x;
    const float* src;
    if (t == 0) src = W_embed;
    else {
        int tt = t - 1, l = tt >> 3, j = tt & 7;
        if (j < 3)      src = Wm + (size_t)l * 384 * HID + j * 16384;
        else if (j < 6) src = We + (size_t)l * 384 * HID + (j - 3) * 16384;
        else            src = Wh + (size_t)l * 256 * HID + (j - 6) * 16384;
    }
    char* dst = (char*)(g_Bw + (size_t)t * 4352);
    for (int i = threadIdx.x; i < 16384; i += 256) {
        int k = i >> 7, n = i & 127;
        float v = src[i];
        __nv_bfloat16 h = __float2bfloat16_rn(v);
        __nv_bfloat16 lo = __float2bfloat16_rn(v - __bfloat162float(h));
        uint32_t off = (uint32_t)(n * LDB + k * 2);
        *(__nv_bfloat16*)(dst + off) = h;
        *(__nv_bfloat16*)(dst + TILE_BYTES + off) = lo;
    }
}

// ---------------------------------------------------------------------------
// proj_gemm: grid (4, GY). P[:, y*128:(y+1)*128] = h @ Wblock[y], m grid-stride
// ---------------------------------------------------------------------------
__global__ __launch_bounds__(GT, 2)
void proj_gemm(const float* __restrict__ A, int sbase, float* __restrict__ C)
{
    extern __shared__ char smem[];
    uint32_t sb = smem_u32(smem);
    const int tid = threadIdx.x, wid = tid >> 5, lane = tid & 31;
    const int y = blockIdx.x;
    const int wm = wid & 3, wn = wid >> 2;
    const int r4 = lane >> 2, c2 = (lane & 3) * 2;

    stage_B(sbase + ((y < 2) ? y : y + 1), tid, smem);
    __syncthreads();

    for (int m0 = blockIdx.y * 128; m0 < N_PAD; m0 += gridDim.y * 128) {
        float acc[2][8][4];
        zero_acc(acc);
        mma_pass<false>(A, m0, sb, wid, lane, acc);

#pragma unroll
        for (int mi = 0; mi < 2; mi++) {
#pragma unroll
            for (int jh = 0; jh < 2; jh++) {
                int row = m0 + wm * 32 + mi * 16 + jh * 8 + r4;
                float* Cp = C + (size_t)row * 512 + y * 128;
#pragma unroll
                for (int ni = 0; ni < 8; ni++) {
                    int col = wn * 64 + ni * 8 + c2;
                    *(float2*)(Cp + col) = make_float2(acc[mi][ni][jh * 2 + 0],
                                                       acc[mi][ni][jh * 2 + 1]);
                }
            }
        }
    }
}

// ---------------------------------------------------------------------------
// dual_gemm: C = A1@B1 (+ A2@B2) + bias, m grid-stride — h embed (GUARD) and h_new
// ---------------------------------------------------------------------------
template<bool GUARD>
__global__ __launch_bounds__(GT, 2)
void dual_gemm(const float* __restrict__ A1, int slot1,
               const float* __restrict__ A2, int slot2,
               const float* __restrict__ bias, float* __restrict__ C)
{
    extern __shared__ char smem[];
    uint32_t sb = smem_u32(smem);
    const int tid = threadIdx.x, wid = tid >> 5, lane = tid & 31;
    const int wm = wid & 3, wn = wid >> 2;
    const int r4 = lane >> 2, c2 = (lane & 3) * 2;

    for (int m0 = blockIdx.x * 128; m0 < N_PAD; m0 += gridDim.x * 128) {
        __syncthreads();                    // prior iter readers done
        stage_B(slot1, tid, smem);
        __syncthreads();
        float acc[2][8][4];
        zero_acc(acc);
        mma_pass<GUARD>(A1, m0, sb, wid, lane, acc);

        if (A2) {
            __syncthreads();
            stage_B(slot2, tid, smem);
            __syncthreads();
            mma_pass<false>(A2, m0, sb, wid, lane, acc);
        }

#pragma unroll
        for (int mi = 0; mi < 2; mi++) {
#pragma unroll
            for (int jh = 0; jh < 2; jh++) {
                int row = m0 + wm * 32 + mi * 16 + jh * 8 + r4;
                float* Cp = C + (size_t)row * HID;
#pragma unroll
                for (int ni = 0; ni < 8; ni++) {
                    int col = wn * 64 + ni * 8 + c2;
                    float2 b = *(const float2*)(bias + col);
                    *(float2*)(Cp + col) = make_float2(acc[mi][ni][jh * 2 + 0] + b.x,
                                                       acc[mi][ni][jh * 2 + 1] + b.y);
                }
            }
        }
    }
}

// ---------------------------------------------------------------------------
// edge_gemm: grid (2, GY), m grid-stride
//  x==0: msg = e@Wm_e + bm + P[s,0:128] + P[r,128:256]  -> red.add agg[r]
//  x==1: e'  = e@We_e + be + P[s,256:384] + P[r,384:512] -> e_out
// ---------------------------------------------------------------------------
__global__ __launch_bounds__(GT, 2)
void edge_gemm(const float* __restrict__ E_in, int slot_m, int slot_e,
               const float* __restrict__ bm, const float* __restrict__ be,
               const float* __restrict__ P,
               const int* __restrict__ send, const int* __restrict__ rec,
               float* __restrict__ agg, float* __restrict__ e_out)
{
    extern __shared__ char smem[];
    uint32_t sb = smem_u32(smem);
    const int tid = threadIdx.x, wid = tid >> 5, lane = tid & 31;
    const int which = blockIdx.x;
    const int wm = wid & 3, wn = wid >> 2;
    const int r4 = lane >> 2, c2 = (lane & 3) * 2;

    stage_B(which ? slot_e : slot_m, tid, smem);
    __syncthreads();

    for (int m0 = blockIdx.y * 128; m0 < N_EDGES; m0 += gridDim.y * 128) {
        float acc[2][8][4];
        zero_acc(acc);
        mma_pass<false>(E_in, m0, sb, wid, lane, acc);

        if (which == 0) {
#pragma unroll
            for (int mi = 0; mi < 2; mi++) {
#pragma unroll
                for (int jh = 0; jh < 2; jh++) {
                    int row = m0 + wm * 32 + mi * 16 + jh * 8 + r4;
                    int s = send[row], r = rec[row];
                    const float* Ps = P + (size_t)s * 512;
                    const float* Pr = P + (size_t)r * 512 + 128;
                    float* ap = agg + (size_t)r * HID;
#pragma unroll
                    for (int ni = 0; ni < 8; ni++) {
                        int col = wn * 64 + ni * 8 + c2;
                        float2 b = *(const float2*)(bm + col);
                        float2 p = *(const float2*)(Ps + col);
                        float2 q = *(const float2*)(Pr + col);
                        red_add_v2(ap + col,
                                   acc[mi][ni][jh * 2 + 0] + b.x + p.x + q.x,
                                   acc[mi][ni][jh * 2 + 1] + b.y + p.y + q.y);
                    }
                }
            }
        } else {
#pragma unroll
            for (int mi = 0; mi < 2; mi++) {
#pragma unroll
                for (int jh = 0; jh < 2; jh++) {
                    int row = m0 + wm * 32 + mi * 16 + jh * 8 + r4;
                    int s = send[row], r = rec[row];
                    const float* Ps = P + (size_t)s * 512 + 256;
                    const float* Pr = P + (size_t)r * 512 + 384;
                    float* op = e_out + (size_t)row * HID;
#pragma unroll
                    for (int ni = 0; ni < 8; ni++) {
                        int col = wn * 64 + ni * 8 + c2;
                        float2 b = *(const float2*)(be + col);
                        float2 p = *(const float2*)(Ps + col);
                        float2 q = *(const float2*)(Pr + col);
                        *(float2*)(op + col) = make_float2(
                            acc[mi][ni][jh * 2 + 0] + b.x + p.x + q.x,
                            acc[mi][ni][jh * 2 + 1] + b.y + p.y + q.y);
                    }
                }
            }
        }
    }
}

// ---------------------------------------------------------------------------
// Edge embedding: e0 = E[:,0:16] @ W[16,128] + b
// ---------------------------------------------------------------------------
__global__ __launch_bounds__(128)
void embed_e_kernel(const float* __restrict__ e_in, const float* __restrict__ W,
                    const float* __restrict__ b, float* __restrict__ out)
{
    __shared__ float Ws[16 * 128];
    __shared__ float bs[128];
    for (int i = threadIdx.x; i < 16 * 128; i += blockDim.x) Ws[i] = W[i];
    if (threadIdx.x < 128) bs[threadIdx.x] = b[threadIdx.x];
    __syncthreads();
    const int c = threadIdx.x;
    for (int k = blockIdx.x; k < N_EDGES; k += gridDim.x) {
        const float* er = e_in + (size_t)k * 16;
        float acc = bs[c];
#pragma unroll
        for (int j = 0; j < 16; j++) acc += er[j] * Ws[j * 128 + c];
        out[(size_t)k * HID + c] = acc;
    }
}

__global__ __launch_bounds__(128)
void pool_kernel(const float* __restrict__ h, const int* __restrict__ batch,
                 float* __restrict__ out)
{
    const int n = blockIdx.x;
    const int c = threadIdx.x;
    const int g = batch[n];
    atomicAdd(&out[(size_t)g * HID + c], h[(size_t)n * HID + c]);
}

// ---------------------------------------------------------------------------
// Launch
// ---------------------------------------------------------------------------
extern "C" void kernel_launch(void* const* d_in, const int* in_sizes, int n_in,
                              void* d_out, int out_size)
{
    const float* h_in     = (const float*)d_in[0];
    const float* e_in     = (const float*)d_in[1];
    const int*   edge_idx = (const int*)  d_in[2];
    const int*   batch    = (const int*)  d_in[3];
    const float* W_embed  = (const float*)d_in[4];
    const float* b_embed  = (const float*)d_in[5];
    const float* W_eembed = (const float*)d_in[6];
    const float* b_eembed = (const float*)d_in[7];
    const float* Wm       = (const float*)d_in[8];
    const float* bm       = (const float*)d_in[9];
    const float* Wh       = (const float*)d_in[10];
    const float* bh       = (const float*)d_in[11];
    const float* We       = (const float*)d_in[12];
    const float* be       = (const float*)d_in[13];
    float*       out      = (float*)d_out;

    cudaFuncSetAttribute(proj_gemm,        cudaFuncAttributeMaxDynamicSharedMemorySize, SMEM_SZ);
    cudaFuncSetAttribute(dual_gemm<true>,  cudaFuncAttributeMaxDynamicSharedMemorySize, SMEM_SZ);
    cudaFuncSetAttribute(dual_gemm<false>, cudaFuncAttributeMaxDynamicSharedMemorySize, SMEM_SZ);
    cudaFuncSetAttribute(edge_gemm,        cudaFuncAttributeMaxDynamicSharedMemorySize, SMEM_SZ);

    float *hbuf, *ebuf, *Pp, *aggp;
    cudaGetSymbolAddress((void**)&hbuf, g_h);
    cudaGetSymbolAddress((void**)&ebuf, g_e);
    cudaGetSymbolAddress((void**)&Pp,   g_P);
    cudaGetSymbolAddress((void**)&aggp, g_agg);

    float* hb[2] = { hbuf, hbuf + (size_t)N_PAD * HID };
    float* eb[2] = { ebuf, ebuf + (size_t)N_EDGES * HID };
    const int* send = edge_idx;
    const int* rec  = edge_idx + N_EDGES;

    // Weight prep + embeddings
    prep_weights<<<33, 256>>>(W_embed, Wm, Wh, We);
    embed_e_kernel<<<2048, 128>>>(e_in, W_eembed, b_eembed, eb[0]);
    dual_gemm<true><<<296, GT, SMEM_SZ>>>(h_in, 0, nullptr, 0, b_embed, hb[0]);

    int cur = 0;
    for (int l = 0; l < N_LAYERS; l++) {
        int sbase = 1 + l * 8;
        const float* bm_l = bm + (size_t)l * HID;
        const float* bh_l = bh + (size_t)l * HID;
        const float* be_l = be + (size_t)l * HID;
        float* hcur = hb[cur];
        float* ecur = eb[cur];
        float* hnxt = hb[1 - cur];
        float* enxt = eb[1 - cur];

        // P = h @ [Wm_s | Wm_r | We_s | We_r]  -> [N, 512]
        proj_gemm<<<dim3(4, 148), GT, SMEM_SZ>>>(hcur, sbase, Pp);

        cudaMemsetAsync(aggp, 0, (size_t)N_PAD * HID * sizeof(float));

        // Fused edge GEMMs: x=0 message+scatter, x=1 edge update (B staged once/CTA)
        edge_gemm<<<dim3(2, 592), GT, SMEM_SZ>>>(
            ecur, sbase + 2, sbase + 5, bm_l, be_l, Pp, send, rec, aggp, enxt);

        // h_new = [h | agg] @ Wh + bh
        dual_gemm<false><<<296, GT, SMEM_SZ>>>(hcur, sbase + 6, aggp, sbase + 7, bh_l, hnxt);

        cur = 1 - cur;
    }

    cudaMemsetAsync(d_out, 0, (size_t)NUM_GRAPHS * HID * sizeof(float));
    pool_kernel<<<N_NODES, 128>>>(hb[cur], batch, out);
}